// round 11
// baseline (speedup 1.0000x reference)
#include <cuda_runtime.h>
#include <cuda_bf16.h>

// Problem: GeneratingReconstructionLoss
//   p:      (16, 256)        float32   (4096 elems)
//   y_pred: (16, 256, 32000) float32   (131,072,000 elems)
//   y_true: (256,)           int32     (JAX x64 disabled: int64 -> int32)
//   out = sum(p * ce) / 256,  ce[n,b] = logsumexp(y_pred[n,b,:]) - y_pred[n,b,y_true[b]]
//
// Measured scoreboard (all DRAM-saturated at 6.43-6.47 TB/s, 81-82%):
//   R4 two-kernel 4096x256:  80.19us
//   R5 fused      4096x256:  80.38us
//   R8 fused      4096x320:  81.50us  (raggedness theory falsified)
//   R10 split-row 8192x256:  80.64us  (drain-tail theory falsified)
// => ~6.45 TB/s is the practical ceiling for this read-once fp32 stream.
// R11: revert to best shape (fused 4096x256, no split-row atomics) + deepen
// per-thread MLP with unroll 8 (8 front-batched LDG.128/thread).

#define VOCAB       32000
#define N_STEPS     16
#define BATCH_SZ    256
#define N_ROWS      (N_STEPS * BATCH_SZ)   // 4096
#define VEC_PER_ROW (VOCAB / 4)            // 8000
#define CTA_THREADS 256
#define N_WARPS     (CTA_THREADS / 32)

__device__ float        g_partials[N_ROWS];
__device__ unsigned int g_ticket = 0;

__global__ __launch_bounds__(CTA_THREADS)
void ce_fused_kernel(const float* __restrict__ p,
                     const float* __restrict__ y_pred,
                     const int* __restrict__ y_true,
                     float* __restrict__ out)
{
    const int row = blockIdx.x;                       // n*BATCH + b
    const float4* __restrict__ x4 =
        reinterpret_cast<const float4*>(y_pred + (size_t)row * VOCAB);

    // 8000 vec4 / 256 thr = 31.25 iters/thread; unroll 8 front-batches
    // 8 LDG.128 per thread for deeper MLP
    float s0 = 0.0f, s1 = 0.0f;
    #pragma unroll 8
    for (int i = threadIdx.x; i < VEC_PER_ROW; i += CTA_THREADS) {
        float4 v = __ldcs(&x4[i]);   // streaming: read-once, 4x larger than L2
        s0 += __expf(v.x) + __expf(v.y);
        s1 += __expf(v.z) + __expf(v.w);
    }
    float s = s0 + s1;

    // thread 0: issue scalar tail loads early, before the reduction wait
    float p_row = 0.0f;
    float x_tgt = 0.0f;
    if (threadIdx.x == 0) {
        const int b = row & (BATCH_SZ - 1);
        int tgt = __ldg(&y_true[b]);
        if (tgt < 0) tgt = 0;                 // defensive: OOB -> rel_err, not IMA
        if (tgt >= VOCAB) tgt = VOCAB - 1;
        x_tgt = __ldg(&y_pred[(size_t)row * VOCAB + (size_t)tgt]);
        p_row = __ldg(&p[row]);
    }

    // intra-warp reduce
    #pragma unroll
    for (int o = 16; o > 0; o >>= 1)
        s += __shfl_xor_sync(0xffffffffu, s, o);

    __shared__ float warp_sums[N_WARPS];
    __shared__ bool  is_last;
    const int wid = threadIdx.x >> 5;
    const int lid = threadIdx.x & 31;
    if (lid == 0) warp_sums[wid] = s;
    __syncthreads();

    if (threadIdx.x == 0) {
        float tot = 0.0f;
        #pragma unroll
        for (int w = 0; w < N_WARPS; ++w) tot += warp_sums[w];
        const float ce = __logf(tot) - x_tgt;
        g_partials[row] = p_row * ce;

        __threadfence();  // make partial visible before taking a ticket
        unsigned int prev = atomicAdd(&g_ticket, 1u);
        is_last = (prev == (unsigned int)(gridDim.x - 1));
    }
    __syncthreads();

    if (is_last) {
        // last CTA: deterministic fixed-order reduction of all partials
        float r = 0.0f;
        #pragma unroll
        for (int i = threadIdx.x; i < N_ROWS; i += CTA_THREADS)
            r += g_partials[i];

        #pragma unroll
        for (int o = 16; o > 0; o >>= 1)
            r += __shfl_xor_sync(0xffffffffu, r, o);

        if (lid == 0) warp_sums[wid] = r;
        __syncthreads();

        if (threadIdx.x == 0) {
            float tot = 0.0f;
            #pragma unroll
            for (int w = 0; w < N_WARPS; ++w) tot += warp_sums[w];
            out[0] = tot * (1.0f / (float)BATCH_SZ);
            g_ticket = 0;   // reset for next graph replay
        }
    }
}

extern "C" void kernel_launch(void* const* d_in, const int* in_sizes, int n_in,
                              void* d_out, int out_size)
{
    // Identify inputs by element count (robust to metadata ordering):
    //   p: 4096, y_pred: 131072000, y_true: 256
    const float* p      = nullptr;
    const float* y_pred = nullptr;
    const int*   y_true = nullptr;
    for (int i = 0; i < n_in; ++i) {
        if (in_sizes[i] == N_ROWS)            p      = (const float*)d_in[i];
        else if (in_sizes[i] == BATCH_SZ)     y_true = (const int*)d_in[i];
        else                                  y_pred = (const float*)d_in[i];
    }
    float* out = (float*)d_out;

    ce_fused_kernel<<<N_ROWS, CTA_THREADS>>>(p, y_pred, y_true, out);
}

// round 13
// speedup vs baseline: 1.0195x; 1.0195x over previous
#include <cuda_runtime.h>
#include <cuda_bf16.h>

// Problem: GeneratingReconstructionLoss
//   p:      (16, 256)        float32   (4096 elems)
//   y_pred: (16, 256, 32000) float32   (131,072,000 elems)
//   y_true: (256,)           int32     (JAX x64 disabled: int64 -> int32)
//   out = sum(p * ce) / 256,  ce[n,b] = logsumexp(y_pred[n,b,:]) - y_pred[n,b,y_true[b]]
//
// Measured scoreboard (all DRAM-saturated at 6.43-6.47 TB/s, 81-82%):
//   R4  two-kernel 4096x256 u4:  80.19us   <- best
//   R5  fused      4096x256 u4:  80.38us
//   R8  fused      4096x320 u5:  81.50us   (raggedness falsified)
//   R10 split-row  8192x256 u4:  80.64us   (drain-tail falsified)
//   R11 fused      4096x256 u8:  81.98us   (deep unroll falsified)
// => unroll 4 @ 256 thr is optimal; plateau = read-path ceiling.
// R12 A/B: drop __ldcs (the one never-tested variable). Evict-first may
// hurt the 4096-point target-logit gather that re-reads freshly streamed
// lines from L2. Default policy costs nothing on a read-once stream.

#define VOCAB       32000
#define N_STEPS     16
#define BATCH_SZ    256
#define N_ROWS      (N_STEPS * BATCH_SZ)   // 4096
#define VEC_PER_ROW (VOCAB / 4)            // 8000
#define CTA_THREADS 256
#define N_WARPS     (CTA_THREADS / 32)

__device__ float        g_partials[N_ROWS];
__device__ unsigned int g_ticket = 0;

__global__ __launch_bounds__(CTA_THREADS)
void ce_fused_kernel(const float* __restrict__ p,
                     const float* __restrict__ y_pred,
                     const int* __restrict__ y_true,
                     float* __restrict__ out)
{
    const int row = blockIdx.x;                       // n*BATCH + b
    const float4* __restrict__ x4 =
        reinterpret_cast<const float4*>(y_pred + (size_t)row * VOCAB);

    float s0 = 0.0f, s1 = 0.0f;
    #pragma unroll 4
    for (int i = threadIdx.x; i < VEC_PER_ROW; i += CTA_THREADS) {
        float4 v = x4[i];            // default cache policy (A/B vs __ldcs)
        s0 += __expf(v.x) + __expf(v.y);
        s1 += __expf(v.z) + __expf(v.w);
    }
    float s = s0 + s1;

    // thread 0: issue scalar tail loads early, before the reduction wait
    float p_row = 0.0f;
    float x_tgt = 0.0f;
    if (threadIdx.x == 0) {
        const int b = row & (BATCH_SZ - 1);
        int tgt = y_true[b];
        if (tgt < 0) tgt = 0;                 // defensive: OOB -> rel_err, not IMA
        if (tgt >= VOCAB) tgt = VOCAB - 1;
        x_tgt = y_pred[(size_t)row * VOCAB + (size_t)tgt];
        p_row = p[row];
    }

    // intra-warp reduce
    #pragma unroll
    for (int o = 16; o > 0; o >>= 1)
        s += __shfl_xor_sync(0xffffffffu, s, o);

    __shared__ float warp_sums[N_WARPS];
    __shared__ bool  is_last;
    const int wid = threadIdx.x >> 5;
    const int lid = threadIdx.x & 31;
    if (lid == 0) warp_sums[wid] = s;
    __syncthreads();

    if (threadIdx.x == 0) {
        float tot = 0.0f;
        #pragma unroll
        for (int w = 0; w < N_WARPS; ++w) tot += warp_sums[w];
        const float ce = __logf(tot) - x_tgt;
        g_partials[row] = p_row * ce;

        __threadfence();  // make partial visible before taking a ticket
        unsigned int prev = atomicAdd(&g_ticket, 1u);
        is_last = (prev == (unsigned int)(gridDim.x - 1));
    }
    __syncthreads();

    if (is_last) {
        // last CTA: deterministic fixed-order reduction of all partials
        float r = 0.0f;
        #pragma unroll
        for (int i = threadIdx.x; i < N_ROWS; i += CTA_THREADS)
            r += g_partials[i];

        #pragma unroll
        for (int o = 16; o > 0; o >>= 1)
            r += __shfl_xor_sync(0xffffffffu, r, o);

        if (lid == 0) warp_sums[wid] = r;
        __syncthreads();

        if (threadIdx.x == 0) {
            float tot = 0.0f;
            #pragma unroll
            for (int w = 0; w < N_WARPS; ++w) tot += warp_sums[w];
            out[0] = tot * (1.0f / (float)BATCH_SZ);
            g_ticket = 0;   // reset for next graph replay
        }
    }
}

extern "C" void kernel_launch(void* const* d_in, const int* in_sizes, int n_in,
                              void* d_out, int out_size)
{
    // Identify inputs by element count (robust to metadata ordering):
    //   p: 4096, y_pred: 131072000, y_true: 256
    const float* p      = nullptr;
    const float* y_pred = nullptr;
    const int*   y_true = nullptr;
    for (int i = 0; i < n_in; ++i) {
        if (in_sizes[i] == N_ROWS)            p      = (const float*)d_in[i];
        else if (in_sizes[i] == BATCH_SZ)     y_true = (const int*)d_in[i];
        else                                  y_pred = (const float*)d_in[i];
    }
    float* out = (float*)d_out;

    ce_fused_kernel<<<N_ROWS, CTA_THREADS>>>(p, y_pred, y_true, out);
}